// round 8
// baseline (speedup 1.0000x reference)
#include <cuda_runtime.h>
#include <cstdint>

#define BH   32
#define S    2048
#define D    64
#define TQ   16
#define NT   512
#define SCP  2052            // score row stride (floats)
#define KVP  68              // K/V tile row stride
#define QSP  68
#define RMP  18              // rowmax stride
#define TILE_R 128
#define NTILES (S / TILE_R)          // 16
#define TILE_FLOATS (TILE_R * KVP)   // 8704
#define NEG_INF_F (-1e10f)
#define SCALE     (0.125f)

#define SC_FLOATS  (TQ * SCP)        // 32832
#define SMEM_FLOATS (SC_FLOATS + 2 * TILE_FLOATS + TQ * QSP + 16 * RMP + TQ + 32)
#define SMEM_BYTES  (SMEM_FLOATS * 4)

// exact 2-term split via mantissa truncation (ALU LOP3, not F2FP)
__device__ __forceinline__ void split_tf32(float a, uint32_t& hi, uint32_t& lo) {
    uint32_t h = __float_as_uint(a) & 0xFFFFE000u;
    hi = h;
    lo = __float_as_uint(a - __uint_as_float(h));
}

__device__ __forceinline__ void mma_tf32(float* c,
                                         uint32_t a0, uint32_t a1, uint32_t a2, uint32_t a3,
                                         uint32_t b0, uint32_t b1) {
    asm volatile(
        "mma.sync.aligned.m16n8k8.row.col.f32.tf32.tf32.f32 "
        "{%0,%1,%2,%3},{%4,%5,%6,%7},{%8,%9},{%0,%1,%2,%3};"
        : "+f"(c[0]), "+f"(c[1]), "+f"(c[2]), "+f"(c[3])
        : "r"(a0), "r"(a1), "r"(a2), "r"(a3), "r"(b0), "r"(b1));
}

__device__ __forceinline__ void cp_tile(const float4* gsrc, float* buf, int t) {
    #pragma unroll
    for (int i = 0; i < 4; ++i) {
        int fidx = t + i * NT;
        int kr = fidx >> 4, d4 = fidx & 15;
        uint32_t sm = (uint32_t)__cvta_generic_to_shared(buf + kr * KVP + d4 * 4);
        asm volatile("cp.async.cg.shared.global [%0], [%1], 16;" :: "r"(sm), "l"(gsrc + fidx));
    }
    asm volatile("cp.async.commit_group;");
}

__device__ __forceinline__ void cp_wait_all() {
    asm volatile("cp.async.wait_group 0;" ::: "memory");
}

__global__ __launch_bounds__(NT, 1)
void dist_attn_kernel(const float* __restrict__ Q,
                      const float* __restrict__ K,
                      const float* __restrict__ V,
                      const float* __restrict__ dist,
                      const int* __restrict__ mask,
                      float* __restrict__ ctx,
                      float* __restrict__ attn)
{
    extern __shared__ float sm[];
    float* sc     = sm;                       // [TQ][SCP] masked scaled scores -> probs
    float* bufA   = sm + SC_FLOATS;
    float* bufB   = bufA + TILE_FLOATS;
    float* Qs     = bufB + TILE_FLOATS;       // [TQ][QSP]
    float* rowmax = Qs + TQ * QSP;            // [16 warps][RMP]
    float* invs   = rowmax + 16 * RMP;        // [TQ]

    const int t    = threadIdx.x;
    const int warp = t >> 5;
    const int lane = t & 31;
    const int gid  = lane >> 2;
    const int tig  = lane & 3;
    const int bh = blockIdx.y;
    const int q0 = blockIdx.x * TQ;
    const size_t rowbase = (size_t)bh * S;

    const float4* Kg4 = (const float4*)(K + rowbase * D);
    const float4* Vg4 = (const float4*)(V + rowbase * D);

    cp_tile(Kg4, bufA, t);

    if (t < 256) {
        const float4 v = ((const float4*)(Q + (rowbase + q0) * D))[t];
        int qr = t >> 4, d4 = t & 15;
        *(float4*)(Qs + qr * QSP + d4 * 4) = v;
    }
    __syncthreads();

    // persistent Q A-fragments (hi/lo), 8 k-steps
    uint32_t qhi[8][4], qlo[8][4];
    #pragma unroll
    for (int ks = 0; ks < 8; ++ks) {
        float a0 = Qs[gid * QSP       + ks * 8 + tig];
        float a1 = Qs[(gid + 8) * QSP + ks * 8 + tig];
        float a2 = Qs[gid * QSP       + ks * 8 + tig + 4];
        float a3 = Qs[(gid + 8) * QSP + ks * 8 + tig + 4];
        split_tf32(a0, qhi[ks][0], qlo[ks][0]);
        split_tf32(a1, qhi[ks][1], qlo[ks][1]);
        split_tf32(a2, qhi[ks][2], qlo[ks][2]);
        split_tf32(a3, qhi[ks][3], qlo[ks][3]);
    }

    // ============ Phase 1: scores = Q@K^T fused with dist/mask/scale + row-max ============
    const size_t row0g = rowbase + q0 + gid;
    float m0 = -3.4e38f, m1 = -3.4e38f;

    for (int p = 0; p < NTILES; ++p) {
        float* cur = (p & 1) ? bufB : bufA;
        float* nxt = (p & 1) ? bufA : bufB;
        cp_wait_all();
        __syncthreads();
        if (p < NTILES - 1) cp_tile(Kg4 + (p + 1) * (TILE_R * D / 4), nxt, t);

        const int col = p * TILE_R + warp * 8 + 2 * tig;
        float2 d0 = *(const float2*)(dist + row0g * S + col);
        float2 d1 = *(const float2*)(dist + (row0g + 8) * S + col);
        int2   k0 = *(const int2*)(mask + row0g * S + col);
        int2   k1 = *(const int2*)(mask + (row0g + 8) * S + col);

        float aHH[4] = {0,0,0,0}, aHL[4] = {0,0,0,0}, aLH[4] = {0,0,0,0};
        const float* kb = cur + (warp * 8 + gid) * KVP + tig;
        #pragma unroll
        for (int ks = 0; ks < 8; ++ks) {
            float b0f = kb[ks * 8];
            float b1f = kb[ks * 8 + 4];
            uint32_t bh0, bl0, bh1, bl1;
            split_tf32(b0f, bh0, bl0);
            split_tf32(b1f, bh1, bl1);
            mma_tf32(aHH, qhi[ks][0], qhi[ks][1], qhi[ks][2], qhi[ks][3], bh0, bh1);
            mma_tf32(aHL, qhi[ks][0], qhi[ks][1], qhi[ks][2], qhi[ks][3], bl0, bl1);
            mma_tf32(aLH, qlo[ks][0], qlo[ks][1], qlo[ks][2], qlo[ks][3], bh0, bh1);
        }
        float s0 = aHH[0] + aHL[0] + aLH[0];
        float s1 = aHH[1] + aHL[1] + aLH[1];
        float s2 = aHH[2] + aHL[2] + aLH[2];
        float s3 = aHH[3] + aHL[3] + aLH[3];
        s0 = k0.x ? NEG_INF_F : d0.x * s0 * SCALE;
        s1 = k0.y ? NEG_INF_F : d0.y * s1 * SCALE;
        s2 = k1.x ? NEG_INF_F : d1.x * s2 * SCALE;
        s3 = k1.y ? NEG_INF_F : d1.y * s3 * SCALE;
        m0 = fmaxf(m0, fmaxf(s0, s1));
        m1 = fmaxf(m1, fmaxf(s2, s3));
        *(float2*)(sc + gid * SCP + col)       = make_float2(s0, s1);
        *(float2*)(sc + (gid + 8) * SCP + col) = make_float2(s2, s3);
    }
    #pragma unroll
    for (int o = 1; o <= 2; o <<= 1) {
        m0 = fmaxf(m0, __shfl_xor_sync(0xffffffffu, m0, o));
        m1 = fmaxf(m1, __shfl_xor_sync(0xffffffffu, m1, o));
    }
    if (tig == 0) {
        rowmax[warp * RMP + gid]     = m0;
        rowmax[warp * RMP + gid + 8] = m1;
    }
    __syncthreads();

    // prefetch V tile 0 (overlaps softmax)
    cp_tile(Vg4, bufA, t);

    // ============ Phase 2: exp + row-sum (smem only; no global traffic) ============
    {
        const int q = warp;
        float4* scRow = (float4*)(sc + q * SCP);

        float m = (lane < 16) ? rowmax[lane * RMP + q] : -3.4e38f;
        #pragma unroll
        for (int o = 16; o > 0; o >>= 1)
            m = fmaxf(m, __shfl_xor_sync(0xffffffffu, m, o));

        float sum = 0.f;
        #pragma unroll
        for (int i = 0; i < 16; ++i) {
            int idx = i * 32 + lane;
            float4 s = scRow[idx];
            s.x = __expf(s.x - m); s.y = __expf(s.y - m);
            s.z = __expf(s.z - m); s.w = __expf(s.w - m);
            scRow[idx] = s;                       // unnormalized p
            sum += s.x + s.y + s.z + s.w;
        }
        #pragma unroll
        for (int o = 16; o > 0; o >>= 1)
            sum += __shfl_xor_sync(0xffffffffu, sum, o);
        if (lane == 0) invs[q] = 1.f / sum;
    }
    __syncthreads();

    // ============ Phase 3: context = p @ V + attn write (overlapped) ============
    {
        const float invA = invs[gid];
        const float invB = invs[gid + 8];
        float* attnA = attn + (rowbase + q0 + gid) * S;
        float* attnB = attn + (rowbase + q0 + gid + 8) * S;

        float acc[8][4];
        #pragma unroll
        for (int i = 0; i < 8; ++i)
            #pragma unroll
            for (int j = 0; j < 4; ++j) acc[i][j] = 0.f;

        for (int p = 0; p < NTILES; ++p) {
            float* cur = (p & 1) ? bufB : bufA;
            float* nxt = (p & 1) ? bufA : bufB;
            cp_wait_all();
            __syncthreads();
            if (p < NTILES - 1) cp_tile(Vg4 + (p + 1) * (TILE_R * D / 4), nxt, t);

            const int kcol = p * TILE_R + warp * 8;
            float a0 = sc[gid * SCP       + kcol + tig];
            float a1 = sc[(gid + 8) * SCP + kcol + tig];
            float a2 = sc[gid * SCP       + kcol + tig + 4];
            float a3 = sc[(gid + 8) * SCP + kcol + tig + 4];

            // normalized attn output for this fragment (overlaps MMAs below)
            attnA[kcol + tig]     = a0 * invA;
            attnB[kcol + tig]     = a1 * invB;
            attnA[kcol + tig + 4] = a2 * invA;
            attnB[kcol + tig + 4] = a3 * invB;

            uint32_t Ah[4], Al[4];
            split_tf32(a0, Ah[0], Al[0]);
            split_tf32(a1, Ah[1], Al[1]);
            split_tf32(a2, Ah[2], Al[2]);
            split_tf32(a3, Ah[3], Al[3]);

            const float* vb = cur + (warp * 8 + tig) * KVP + gid;
            #pragma unroll
            for (int nt = 0; nt < 8; ++nt) {
                float b0f = vb[nt * 8];
                float b1f = vb[4 * KVP + nt * 8];
                uint32_t bh0, bl0, bh1, bl1;
                split_tf32(b0f, bh0, bl0);
                split_tf32(b1f, bh1, bl1);
                mma_tf32(acc[nt], Ah[0], Ah[1], Ah[2], Ah[3], bh0, bh1);
                mma_tf32(acc[nt], Ah[0], Ah[1], Ah[2], Ah[3], bl0, bl1);
                mma_tf32(acc[nt], Al[0], Al[1], Al[2], Al[3], bh0, bh1);
            }
        }
        __syncthreads();

        // split-k reduce: red[warp][q][d]
        float* red = bufA;
        #pragma unroll
        for (int nt = 0; nt < 8; ++nt) {
            const int col = nt * 8 + 2 * tig;
            *(float2*)(red + warp * (TQ * KVP) + gid * KVP + col) =
                make_float2(acc[nt][0], acc[nt][1]);
            *(float2*)(red + warp * (TQ * KVP) + (gid + 8) * KVP + col) =
                make_float2(acc[nt][2], acc[nt][3]);
        }
        __syncthreads();

        #pragma unroll
        for (int o = t; o < TQ * D; o += NT) {
            int q = o >> 6, d = o & 63;
            float s = 0.f;
            #pragma unroll
            for (int g = 0; g < 16; ++g)
                s += red[g * (TQ * KVP) + q * KVP + d];
            ctx[(rowbase + q0 + q) * D + d] = s * invs[q];
        }
    }
}

extern "C" void kernel_launch(void* const* d_in, const int* in_sizes, int n_in,
                              void* d_out, int out_size)
{
    const float* Q    = (const float*)d_in[0];
    const float* K    = (const float*)d_in[1];
    const float* V    = (const float*)d_in[2];
    const float* dist = (const float*)d_in[3];
    const int*   mask = (const int*)d_in[4];

    float* ctx  = (float*)d_out;
    float* attn = (float*)d_out + (size_t)BH * S * D;

    cudaFuncSetAttribute(dist_attn_kernel,
                         cudaFuncAttributeMaxDynamicSharedMemorySize,
                         SMEM_BYTES);

    dim3 grid(S / TQ, BH);
    dist_attn_kernel<<<grid, NT, SMEM_BYTES>>>(Q, K, V, dist, mask, ctx, attn);
}

// round 9
// speedup vs baseline: 1.0265x; 1.0265x over previous
#include <cuda_runtime.h>
#include <cstdint>

#define BH   32
#define S    2048
#define D    64
#define TQ   16
#define NT   512
#define SCP  2052            // score row stride (floats)
#define KVP  68              // K/V tile row stride
#define QSP  68
#define RMP  18              // rowmax stride
#define TILE_R 128
#define NTILES (S / TILE_R)          // 16
#define TILE_FLOATS (TILE_R * KVP)   // 8704
#define NEG_INF_F (-1e10f)
#define SCALE     (0.125f)

#define SC_FLOATS  (TQ * SCP)        // 32832
#define SMEM_FLOATS (SC_FLOATS + 2 * TILE_FLOATS + TQ * QSP + 16 * RMP + TQ + 32)
#define SMEM_BYTES  (SMEM_FLOATS * 4)

// exact 2-term split via mantissa truncation (ALU LOP3, not F2FP)
__device__ __forceinline__ void split_tf32(float a, uint32_t& hi, uint32_t& lo) {
    uint32_t h = __float_as_uint(a) & 0xFFFFE000u;
    hi = h;
    lo = __float_as_uint(a - __uint_as_float(h));
}

__device__ __forceinline__ void mma_tf32(float* c,
                                         uint32_t a0, uint32_t a1, uint32_t a2, uint32_t a3,
                                         uint32_t b0, uint32_t b1) {
    asm volatile(
        "mma.sync.aligned.m16n8k8.row.col.f32.tf32.tf32.f32 "
        "{%0,%1,%2,%3},{%4,%5,%6,%7},{%8,%9},{%0,%1,%2,%3};"
        : "+f"(c[0]), "+f"(c[1]), "+f"(c[2]), "+f"(c[3])
        : "r"(a0), "r"(a1), "r"(a2), "r"(a3), "r"(b0), "r"(b1));
}

__device__ __forceinline__ void cp_tile(const float4* gsrc, float* buf, int t) {
    #pragma unroll
    for (int i = 0; i < 4; ++i) {
        int fidx = t + i * NT;
        int kr = fidx >> 4, d4 = fidx & 15;
        uint32_t sm = (uint32_t)__cvta_generic_to_shared(buf + kr * KVP + d4 * 4);
        asm volatile("cp.async.cg.shared.global [%0], [%1], 16;" :: "r"(sm), "l"(gsrc + fidx));
    }
    asm volatile("cp.async.commit_group;");
}

__device__ __forceinline__ void cp_wait_all() {
    asm volatile("cp.async.wait_group 0;" ::: "memory");
}

__global__ __launch_bounds__(NT, 1)
void dist_attn_kernel(const float* __restrict__ Q,
                      const float* __restrict__ K,
                      const float* __restrict__ V,
                      const float* __restrict__ dist,
                      const int* __restrict__ mask,
                      float* __restrict__ ctx,
                      float* __restrict__ attn)
{
    extern __shared__ float sm[];
    float* sc     = sm;                       // [TQ][SCP] masked scaled scores -> probs
    float* bufA   = sm + SC_FLOATS;
    float* bufB   = bufA + TILE_FLOATS;
    float* Qs     = bufB + TILE_FLOATS;       // [TQ][QSP]
    float* rowmax = Qs + TQ * QSP;            // [16 warps][RMP]
    float* invs   = rowmax + 16 * RMP;        // [TQ]

    const int t    = threadIdx.x;
    const int warp = t >> 5;
    const int lane = t & 31;
    const int gid  = lane >> 2;
    const int tig  = lane & 3;
    const int bh = blockIdx.y;
    const int q0 = blockIdx.x * TQ;
    const size_t rowbase = (size_t)bh * S;

    const float4* Kg4 = (const float4*)(K + rowbase * D);
    const float4* Vg4 = (const float4*)(V + rowbase * D);

    cp_tile(Kg4, bufA, t);

    if (t < 256) {
        const float4 v = ((const float4*)(Q + (rowbase + q0) * D))[t];
        int qr = t >> 4, d4 = t & 15;
        *(float4*)(Qs + qr * QSP + d4 * 4) = v;
    }
    __syncthreads();

    // persistent Q A-fragments (hi/lo), 8 k-steps
    uint32_t qhi[8][4], qlo[8][4];
    #pragma unroll
    for (int ks = 0; ks < 8; ++ks) {
        float a0 = Qs[gid * QSP       + ks * 8 + tig];
        float a1 = Qs[(gid + 8) * QSP + ks * 8 + tig];
        float a2 = Qs[gid * QSP       + ks * 8 + tig + 4];
        float a3 = Qs[(gid + 8) * QSP + ks * 8 + tig + 4];
        split_tf32(a0, qhi[ks][0], qlo[ks][0]);
        split_tf32(a1, qhi[ks][1], qlo[ks][1]);
        split_tf32(a2, qhi[ks][2], qlo[ks][2]);
        split_tf32(a3, qhi[ks][3], qlo[ks][3]);
    }

    // ============ Phase 1: scores = Q@K^T fused with dist/mask/scale + row-max ============
    const size_t row0g = rowbase + q0 + gid;
    float m0 = -3.4e38f, m1 = -3.4e38f;

    for (int p = 0; p < NTILES; ++p) {
        float* cur = (p & 1) ? bufB : bufA;
        float* nxt = (p & 1) ? bufA : bufB;

        const int col = p * TILE_R + warp * 8 + 2 * tig;
        // dist/mask loads issued BEFORE the wait+barrier: extra latency overlap
        float2 d0 = *(const float2*)(dist + row0g * S + col);
        float2 d1 = *(const float2*)(dist + (row0g + 8) * S + col);
        int2   k0 = *(const int2*)(mask + row0g * S + col);
        int2   k1 = *(const int2*)(mask + (row0g + 8) * S + col);

        cp_wait_all();
        __syncthreads();
        if (p < NTILES - 1) cp_tile(Kg4 + (p + 1) * (TILE_R * D / 4), nxt, t);

        float aHH[4] = {0,0,0,0}, aHL[4] = {0,0,0,0}, aLH[4] = {0,0,0,0};
        const float* kb = cur + (warp * 8 + gid) * KVP + tig;
        #pragma unroll
        for (int ks = 0; ks < 8; ++ks) {
            float b0f = kb[ks * 8];
            float b1f = kb[ks * 8 + 4];
            uint32_t bh0, bl0, bh1, bl1;
            split_tf32(b0f, bh0, bl0);
            split_tf32(b1f, bh1, bl1);
            mma_tf32(aHH, qhi[ks][0], qhi[ks][1], qhi[ks][2], qhi[ks][3], bh0, bh1);
            mma_tf32(aHL, qhi[ks][0], qhi[ks][1], qhi[ks][2], qhi[ks][3], bl0, bl1);
            mma_tf32(aLH, qlo[ks][0], qlo[ks][1], qlo[ks][2], qlo[ks][3], bh0, bh1);
        }
        float s0 = aHH[0] + aHL[0] + aLH[0];
        float s1 = aHH[1] + aHL[1] + aLH[1];
        float s2 = aHH[2] + aHL[2] + aLH[2];
        float s3 = aHH[3] + aHL[3] + aLH[3];
        s0 = k0.x ? NEG_INF_F : d0.x * s0 * SCALE;
        s1 = k0.y ? NEG_INF_F : d0.y * s1 * SCALE;
        s2 = k1.x ? NEG_INF_F : d1.x * s2 * SCALE;
        s3 = k1.y ? NEG_INF_F : d1.y * s3 * SCALE;
        m0 = fmaxf(m0, fmaxf(s0, s1));
        m1 = fmaxf(m1, fmaxf(s2, s3));
        *(float2*)(sc + gid * SCP + col)       = make_float2(s0, s1);
        *(float2*)(sc + (gid + 8) * SCP + col) = make_float2(s2, s3);
    }
    #pragma unroll
    for (int o = 1; o <= 2; o <<= 1) {
        m0 = fmaxf(m0, __shfl_xor_sync(0xffffffffu, m0, o));
        m1 = fmaxf(m1, __shfl_xor_sync(0xffffffffu, m1, o));
    }
    if (tig == 0) {
        rowmax[warp * RMP + gid]     = m0;
        rowmax[warp * RMP + gid + 8] = m1;
    }
    __syncthreads();

    // prefetch V tile 0 (overlaps softmax)
    cp_tile(Vg4, bufA, t);

    // ============ Phase 2: exp + row-sum (smem only; no global traffic) ============
    {
        const int q = warp;
        float4* scRow = (float4*)(sc + q * SCP);

        float m = (lane < 16) ? rowmax[lane * RMP + q] : -3.4e38f;
        #pragma unroll
        for (int o = 16; o > 0; o >>= 1)
            m = fmaxf(m, __shfl_xor_sync(0xffffffffu, m, o));

        float sum = 0.f;
        #pragma unroll
        for (int i = 0; i < 16; ++i) {
            int idx = i * 32 + lane;
            float4 s = scRow[idx];
            s.x = __expf(s.x - m); s.y = __expf(s.y - m);
            s.z = __expf(s.z - m); s.w = __expf(s.w - m);
            scRow[idx] = s;                       // unnormalized p
            sum += s.x + s.y + s.z + s.w;
        }
        #pragma unroll
        for (int o = 16; o > 0; o >>= 1)
            sum += __shfl_xor_sync(0xffffffffu, sum, o);
        if (lane == 0) invs[q] = 1.f / sum;
    }
    __syncthreads();

    // ============ Phase 3: context = p @ V + coalesced attn write (overlapped) ============
    {
        const float invW = invs[warp];
        float4* attnRowW = (float4*)(attn + (rowbase + q0 + warp) * S);

        float acc[8][4];
        #pragma unroll
        for (int i = 0; i < 8; ++i)
            #pragma unroll
            for (int j = 0; j < 4; ++j) acc[i][j] = 0.f;

        for (int p = 0; p < NTILES; ++p) {
            float* cur = (p & 1) ? bufB : bufA;
            float* nxt = (p & 1) ? bufA : bufB;
            cp_wait_all();
            __syncthreads();
            if (p < NTILES - 1) cp_tile(Vg4 + (p + 1) * (TILE_R * D / 4), nxt, t);

            // coalesced attn chunk: warp w writes row w, this tile's 128 cols
            {
                float4 pv = *(const float4*)(sc + warp * SCP + p * TILE_R + lane * 4);
                attnRowW[p * 32 + lane] =
                    make_float4(pv.x * invW, pv.y * invW, pv.z * invW, pv.w * invW);
            }

            const int kcol = p * TILE_R + warp * 8;
            float a0 = sc[gid * SCP       + kcol + tig];
            float a1 = sc[(gid + 8) * SCP + kcol + tig];
            float a2 = sc[gid * SCP       + kcol + tig + 4];
            float a3 = sc[(gid + 8) * SCP + kcol + tig + 4];
            uint32_t Ah[4], Al[4];
            split_tf32(a0, Ah[0], Al[0]);
            split_tf32(a1, Ah[1], Al[1]);
            split_tf32(a2, Ah[2], Al[2]);
            split_tf32(a3, Ah[3], Al[3]);

            const float* vb = cur + (warp * 8 + tig) * KVP + gid;
            #pragma unroll
            for (int nt = 0; nt < 8; ++nt) {
                float b0f = vb[nt * 8];
                float b1f = vb[4 * KVP + nt * 8];
                uint32_t bh0, bl0, bh1, bl1;
                split_tf32(b0f, bh0, bl0);
                split_tf32(b1f, bh1, bl1);
                mma_tf32(acc[nt], Ah[0], Ah[1], Ah[2], Ah[3], bh0, bh1);
                mma_tf32(acc[nt], Ah[0], Ah[1], Ah[2], Ah[3], bl0, bl1);
                mma_tf32(acc[nt], Al[0], Al[1], Al[2], Al[3], bh0, bh1);
            }
        }
        __syncthreads();

        // split-k reduce: red[warp][q][d]
        float* red = bufA;
        #pragma unroll
        for (int nt = 0; nt < 8; ++nt) {
            const int col = nt * 8 + 2 * tig;
            *(float2*)(red + warp * (TQ * KVP) + gid * KVP + col) =
                make_float2(acc[nt][0], acc[nt][1]);
            *(float2*)(red + warp * (TQ * KVP) + (gid + 8) * KVP + col) =
                make_float2(acc[nt][2], acc[nt][3]);
        }
        __syncthreads();

        #pragma unroll
        for (int o = t; o < TQ * D; o += NT) {
            int q = o >> 6, d = o & 63;
            float s = 0.f;
            #pragma unroll
            for (int g = 0; g < 16; ++g)
                s += red[g * (TQ * KVP) + q * KVP + d];
            ctx[(rowbase + q0 + q) * D + d] = s * invs[q];
        }
    }
}

extern "C" void kernel_launch(void* const* d_in, const int* in_sizes, int n_in,
                              void* d_out, int out_size)
{
    const float* Q    = (const float*)d_in[0];
    const float* K    = (const float*)d_in[1];
    const float* V    = (const float*)d_in[2];
    const float* dist = (const float*)d_in[3];
    const int*   mask = (const int*)d_in[4];

    float* ctx  = (float*)d_out;
    float* attn = (float*)d_out + (size_t)BH * S * D;

    cudaFuncSetAttribute(dist_attn_kernel,
                         cudaFuncAttributeMaxDynamicSharedMemorySize,
                         SMEM_BYTES);

    dim3 grid(S / TQ, BH);
    dist_attn_kernel<<<grid, NT, SMEM_BYTES>>>(Q, K, V, dist, mask, ctx, attn);
}